// round 17
// baseline (speedup 1.0000x reference)
#include <cuda_runtime.h>
#include <cstdint>

#define BB 16
#define SS 4096
#define VV 1024
#define INV_SQRT_S 0.015625f   // 1/sqrt(4096)
#define NB 592                 // 148 SMs x 4 CTAs: exactly one resident wave

// Scratch (no allocations allowed)
__device__ float g_qp[2][BB * VV];   // q partials (v-halves)
__device__ float g_u[BB * VV];
__device__ float g_c[BB];
__device__ float g_y[BB * VV];
__device__ float g_A[BB];

// Device-wide sense-reversal barrier (generation-based: safe across graph replays)
__device__ unsigned g_barcnt = 0;
__device__ volatile unsigned g_bargen = 0;

__device__ __forceinline__ void gbar() {
    __syncthreads();
    if (threadIdx.x == 0) {
        __threadfence();
        unsigned gen = g_bargen;
        if (atomicAdd(&g_barcnt, 1u) == NB - 1u) {
            g_barcnt = 0;
            __threadfence();
            g_bargen = gen + 1u;
        } else {
            while (g_bargen == gen) __nanosleep(64);
        }
    }
    __syncthreads();
    __threadfence();
}

// Reduce acc[0..15] across 32 lanes in 16 SHFLs.
// Returns, on every lane, the full sum for b = (lane >> 1) & 15.
__device__ __forceinline__ float reduce16x32(float* acc, int lane) {
#pragma unroll
    for (int step = 0; step < 4; step++) {
        const int off = 16 >> step;    // 16,8,4,2
        const int half = 8 >> step;    // 8,4,2,1
#pragma unroll
        for (int i = 0; i < half; i++) {
            bool hi = (lane & off) != 0;
            float mine = hi ? acc[i + half] : acc[i];
            float theirs = hi ? acc[i] : acc[i + half];
            acc[i] = mine + __shfl_xor_sync(0xffffffffu, theirs, off);
        }
    }
    return acc[0] + __shfl_xor_sync(0xffffffffu, acc[0], 1);
}

// ---------------------------------------------------------------------------
// Single persistent kernel with cross-phase cp.async weight prefetch:
//   A: q partials (512 blocks; pool staged 4x128v chunks at sh[0..2047]);
//      Wk chunk for B prefetched via cp.async into sh[2048..4095].
//      Blocks 512..591 zero g_u/g_y/g_A/out.
//   B: u = q @ Wk (Wk from smem); c[b] = q[b].bk (16 blocks)
//   C: fused main pass (interleaved rows, __ldcs); ys at sh[3072..4095];
//      Wv chunk for D prefetched via cp.async into sh[0..2047].
//   D: out partials (y staged 4x128v chunks at sh[2048..4095]; Wv from smem)
// ---------------------------------------------------------------------------
__global__ void __launch_bounds__(128, 4) fused_kernel(
        const float* __restrict__ pool, const float* __restrict__ X,
        const float* __restrict__ Wq, const float* __restrict__ bq,
        const float* __restrict__ Wk, const float* __restrict__ bk,
        const float* __restrict__ Wv, const float* __restrict__ bv,
        float* __restrict__ out) {
    const int warp = threadIdx.x >> 5, lane = threadIdx.x & 31;
    __shared__ float sh[4096];   // 16 KB, region-partitioned per phase
    __shared__ float shA;
    float4* const sh4 = (float4*)sh;
    const uint32_t shb = (uint32_t)__cvta_generic_to_shared(sh);

    // ---------- Phase A: q partial over v-half ----------
    if (blockIdx.x < 512) {
        const int vh = blockIdx.x & 1;                 // v-half: 0 or 1
        const int o = (blockIdx.x >> 1) * 4 + warp;    // 0..1023
        const int vbase = vh * 512;
        const float4* pool4 = (const float4*)pool;

        // prefetch this block's Phase-B Wk chunk (16 o x 128 v = 8KB)
        {
            const int o0B = (blockIdx.x >> 3) * 16;
            const int vB = (blockIdx.x & 7) * 128;
#pragma unroll
            for (int k = 0; k < 4; k++) {
                int e = (k * 128 + threadIdx.x) * 4;   // element idx, 16B chunks
                int oo = e >> 7, col = e & 127;
                const float* src = Wk + (size_t)(o0B + oo) * VV + vB + col;
                asm volatile("cp.async.cg.shared.global [%0], [%1], 16;"
                             :: "r"(shb + (2048 + e) * 4), "l"(src));
            }
            asm volatile("cp.async.commit_group;");
        }

        float acc[16];
#pragma unroll
        for (int b = 0; b < 16; b++) acc[b] = 0.f;

#pragma unroll
        for (int ch = 0; ch < 4; ch++) {
            __syncthreads();
            // stage pool chunk 16b x 128v = 8KB at sh[0..2047]
#pragma unroll
            for (int k = 0; k < 4; k++) {
                int i = k * 128 + threadIdx.x;
                int b = i >> 5, v4 = i & 31;
                sh4[i] = pool4[b * 256 + (vbase >> 2) + ch * 32 + v4];
            }
            __syncthreads();
#pragma unroll
            for (int j = 0; j < 4; j++) {
                float w = Wq[(size_t)o * VV + vbase + ch * 128 + j * 32 + lane];
#pragma unroll
                for (int b = 0; b < 16; b++)
                    acc[b] = fmaf(w, sh[b * 128 + j * 32 + lane], acc[b]);
            }
        }
        float r = reduce16x32(acc, lane);
        if (!(lane & 1)) {
            int b = lane >> 1;
            float bqo = (vh == 0) ? bq[o] : 0.f;
            g_qp[vh][(size_t)b * VV + o] = r + bqo;
        }
    } else {
        // blocks 512..591 zero accumulators and the output buffer
        for (int t = (blockIdx.x - 512) * 128 + threadIdx.x; t < BB * VV;
             t += 80 * 128) {
            g_u[t] = 0.f; g_y[t] = 0.f; out[t] = 0.f;
        }
        if (blockIdx.x == 512 && threadIdx.x < BB) g_A[threadIdx.x] = 0.f;
    }
    gbar();

    // ---------- Phase B: u[b][v] = sum_o q[b][o]*Wk[o][v];  c[b] = q[b].bk ----------
    if (blockIdx.x < 512) {
        asm volatile("cp.async.wait_group 0;");
        __syncthreads();                       // Wk visible to all threads

        const int o0 = (blockIdx.x >> 3) * 16;
        const int v = (blockIdx.x & 7) * 128 + threadIdx.x;

        // q chunk [16 b][16 o] at sh[0..255]
#pragma unroll
        for (int k = 0; k < 2; k++) {
            int i = k * 128 + threadIdx.x;
            int b = i >> 4, oo = i & 15;
            size_t idx = (size_t)b * VV + o0 + oo;
            sh[i] = g_qp[0][idx] + g_qp[1][idx];
        }
        __syncthreads();

        float acc[16];
#pragma unroll
        for (int b = 0; b < 16; b++) acc[b] = 0.f;
#pragma unroll
        for (int oo = 0; oo < 16; oo++) {
            float w = sh[2048 + oo * 128 + threadIdx.x];   // Wk from smem
#pragma unroll
            for (int b = 0; b < 16; b++)
                acc[b] = fmaf(sh[b * 16 + oo], w, acc[b]);
        }
#pragma unroll
        for (int b = 0; b < 16; b++)
            atomicAdd(&g_u[(size_t)b * VV + v], acc[b]);
    } else if (blockIdx.x < 528) {
        // c[b] = dot(q[b], bk): one block per b, exact write (no atomics)
        const int b = blockIdx.x - 512;
        float s = 0.f;
#pragma unroll
        for (int j = 0; j < 8; j++) {
            int o = j * 128 + threadIdx.x;
            size_t idx = (size_t)b * VV + o;
            s = fmaf(g_qp[0][idx] + g_qp[1][idx], bk[o], s);
        }
#pragma unroll
        for (int off = 16; off; off >>= 1) s += __shfl_xor_sync(0xffffffffu, s, off);
        if (lane == 0) sh[warp] = s;
        __syncthreads();
        if (threadIdx.x == 0) g_c[b] = sh[0] + sh[1] + sh[2] + sh[3];
    }
    gbar();

    // ---------- Phase C: fused main pass over bert_output ----------
    {
        const int b = blockIdx.x & 15;
        const int grp = blockIdx.x >> 4;          // 0..36
        const int wg = grp * 4 + warp;            // 0..147

        // prefetch this block's Phase-D Wv chunk (4 o x 512 v = 8KB) -> sh[0..2047]
        if (blockIdx.x < 512) {
            const int oD = (blockIdx.x >> 1) * 4;
            const int vbD = (blockIdx.x & 1) * 512;
#pragma unroll
            for (int k = 0; k < 4; k++) {
                int e = (k * 128 + threadIdx.x) * 4;
                int ow = e >> 9, col = e & 511;
                const float* src = Wv + (size_t)(oD + ow) * VV + vbD + col;
                asm volatile("cp.async.cg.shared.global [%0], [%1], 16;"
                             :: "r"(shb + e * 4), "l"(src));
            }
            asm volatile("cp.async.commit_group;");
        }

        float* const ys = sh + 3072;   // block y accumulator (1024 floats)

        float4 u4[8];
        const float4* ub = (const float4*)(g_u + (size_t)b * VV);
#pragma unroll
        for (int j = 0; j < 8; j++) u4[j] = ub[j * 32 + lane];
        const float cb = g_c[b];

        float yacc[32];
#pragma unroll
        for (int i = 0; i < 32; i++) yacc[i] = 0.f;
        float Aacc = 0.f;

        const float4* Xb = (const float4*)(X + (size_t)b * SS * VV);
        for (int row = wg; row < SS; row += 148) {
            const float4* xr = Xb + (size_t)row * (VV / 4);
            float4 x4[8];
#pragma unroll
            for (int j = 0; j < 8; j++) x4[j] = __ldcs(&xr[j * 32 + lane]);

            float p[8];
#pragma unroll
            for (int j = 0; j < 8; j++)
                p[j] = fmaf(x4[j].w, u4[j].w,
                       fmaf(x4[j].z, u4[j].z,
                       fmaf(x4[j].y, u4[j].y, x4[j].x * u4[j].x)));
            float d = ((p[0] + p[1]) + (p[2] + p[3])) + ((p[4] + p[5]) + (p[6] + p[7]));
#pragma unroll
            for (int off = 16; off; off >>= 1) d += __shfl_xor_sync(0xffffffffu, d, off);

            const float a = (d + cb) * INV_SQRT_S;
            Aacc += a;
#pragma unroll
            for (int j = 0; j < 8; j++) {
                yacc[j * 4 + 0] = fmaf(a, x4[j].x, yacc[j * 4 + 0]);
                yacc[j * 4 + 1] = fmaf(a, x4[j].y, yacc[j * 4 + 1]);
                yacc[j * 4 + 2] = fmaf(a, x4[j].z, yacc[j * 4 + 2]);
                yacc[j * 4 + 3] = fmaf(a, x4[j].w, yacc[j * 4 + 3]);
            }
        }

        for (int i = threadIdx.x; i < VV; i += 128) ys[i] = 0.f;
        if (threadIdx.x == 0) shA = 0.f;
        __syncthreads();
#pragma unroll
        for (int j = 0; j < 8; j++) {
            int col = j * 128 + lane * 4;
            atomicAdd(&ys[col + 0], yacc[j * 4 + 0]);
            atomicAdd(&ys[col + 1], yacc[j * 4 + 1]);
            atomicAdd(&ys[col + 2], yacc[j * 4 + 2]);
            atomicAdd(&ys[col + 3], yacc[j * 4 + 3]);
        }
        if (lane == 0) atomicAdd(&shA, Aacc);
        __syncthreads();
        for (int i = threadIdx.x; i < VV; i += 128)
            atomicAdd(&g_y[(size_t)b * VV + i], ys[i]);
        if (threadIdx.x == 0) atomicAdd(&g_A[b], shA);
    }
    gbar();

    // ---------- Phase D: out partial over v-half (Wv from smem) ----------
    if (blockIdx.x < 512) {
        asm volatile("cp.async.wait_group 0;");
        __syncthreads();                       // Wv visible to all threads

        const int vh = blockIdx.x & 1;
        const int o = (blockIdx.x >> 1) * 4 + warp;
        const int vbase = vh * 512;
        const float4* y4 = (const float4*)g_y;
        float acc[16];
#pragma unroll
        for (int b = 0; b < 16; b++) acc[b] = 0.f;

#pragma unroll
        for (int ch = 0; ch < 4; ch++) {
            __syncthreads();
            // stage y chunk 16b x 128v = 8KB at sh[2048..4095]
#pragma unroll
            for (int k = 0; k < 4; k++) {
                int i = k * 128 + threadIdx.x;
                int b = i >> 5, v4 = i & 31;
                sh4[512 + i] = y4[b * 256 + (vbase >> 2) + ch * 32 + v4];
            }
            __syncthreads();
#pragma unroll
            for (int j = 0; j < 4; j++) {
                float w = sh[warp * 512 + ch * 128 + j * 32 + lane];  // Wv smem
#pragma unroll
                for (int b = 0; b < 16; b++)
                    acc[b] = fmaf(w, sh[2048 + b * 128 + j * 32 + lane], acc[b]);
            }
        }
        float r = reduce16x32(acc, lane);
        if (!(lane & 1)) {
            int b = lane >> 1;
            float r2 = r + ((vh == 0) ? g_A[b] * bv[o] : 0.f);
            atomicAdd(&out[(size_t)b * VV + o], r2);
        }
    }
}

// ---------------------------------------------------------------------------
extern "C" void kernel_launch(void* const* d_in, const int* in_sizes, int n_in,
                              void* d_out, int out_size) {
    const float* pool = (const float*)d_in[0];
    const float* bert = (const float*)d_in[1];
    const float* Wq   = (const float*)d_in[2];
    const float* bq   = (const float*)d_in[3];
    const float* Wk   = (const float*)d_in[4];
    const float* bk   = (const float*)d_in[5];
    const float* Wv   = (const float*)d_in[6];
    const float* bv   = (const float*)d_in[7];
    float* out = (float*)d_out;

    fused_kernel<<<NB, 128>>>(pool, bert, Wq, bq, Wk, bk, Wv, bv, out);
}